// round 12
// baseline (speedup 1.0000x reference)
#include <cuda_runtime.h>
#include <math.h>

#define V_   100000
#define D_   128
#define B_   4096
#define NEG_ 5
#define DI_  170
#define DIP_ 176
#define BT_  16
#define NBLK (B_ / BT_)      // 256
#define THREADS 512
#define SQRTD 11.3137084989847604f

typedef unsigned long long u64;

__device__ __forceinline__ u64 fma2(u64 a, u64 b, u64 c) {
    u64 d;
    asm("fma.rn.f32x2 %0, %1, %2, %3;" : "=l"(d) : "l"(a), "l"(b), "l"(c));
    return d;
}
__device__ __forceinline__ u64 pk2(float lo, float hi) {
    u64 r;
    asm("mov.b64 %0, {%1, %2};" : "=l"(r) : "f"(lo), "f"(hi));
    return r;
}
__device__ __forceinline__ float2 unpk(u64 v) {
    float2 r;
    asm("mov.b64 {%0, %1}, %2;" : "=f"(r.x), "=f"(r.y) : "l"(v));
    return r;
}
__device__ __forceinline__ float silu_mul(u64 ha, u64 ga) {
    float2 hp = unpk(ha), gp = unpk(ga);
    float h = hp.x + hp.y, g = gp.x + gp.y;
    return h * (g / (1.f + __expf(-g)));
}

// ---- device scratch (prep-written, main-exact layouts) ----
__device__ __align__(16) float4 g_WhgP[DIP_ * 65];   // interleaved normalized Wh/Wg (rows >=170 zero)
__device__ __align__(16) float  g_WffT[DIP_ * D_];   // transposed inv-prescaled Wff (rows >=170 zero)
__device__ float g_partial[NBLK];
__device__ unsigned int g_ticket;

// ------------------------------------------------------------------
// Prep: 176 blocks x 96 threads.
// ------------------------------------------------------------------
__global__ __launch_bounds__(96) void prep_kernel(
    const float* __restrict__ Wh, const float* __restrict__ Wg,
    const float* __restrict__ Wff,
    const float* __restrict__ hs, const float* __restrict__ gs)
{
    int r    = blockIdx.x;               // 0..175
    int mat  = threadIdx.x >> 5;
    int lane = threadIdx.x & 31;

    if (mat < 2) {
        float4 o = make_float4(0.f, 0.f, 0.f, 0.f);
        if (r < DI_) {
            const float4* W = (const float4*)(mat ? Wg : Wh);
            float4 v = W[r * 32 + lane];
            float ss = v.x * v.x + v.y * v.y + v.z * v.z + v.w * v.w;
            #pragma unroll
            for (int o2 = 16; o2; o2 >>= 1) ss += __shfl_xor_sync(0xffffffffu, ss, o2);
            float sc = rsqrtf(ss) * (mat ? gs[r] * SQRTD : hs[r]);
            o = make_float4(v.x * sc, v.y * sc, v.z * sc, v.w * sc);
        }
        g_WhgP[r * 65 + lane * 2 + mat] = o;
    } else {
        if (r < DI_) {
            float v[4]; float ss = 0.f;
            #pragma unroll
            for (int k = 0; k < 4; k++) {
                v[k] = Wff[(lane + 32 * k) * DI_ + r];
                ss += v[k] * v[k];
            }
            #pragma unroll
            for (int o2 = 16; o2; o2 >>= 1) ss += __shfl_xor_sync(0xffffffffu, ss, o2);
            float inv = rsqrtf(ss);
            #pragma unroll
            for (int k = 0; k < 4; k++)
                g_WffT[r * D_ + lane + 32 * k] = v[k] * inv;
        } else {
            #pragma unroll
            for (int k = 0; k < 4; k++)
                g_WffT[r * D_ + lane + 32 * k] = 0.f;
        }
    }
}

// ------------------------------------------------------------------
// Main: 256 blocks x 512 threads, 16 batch rows/block, 2 blocks/SM.
//
// smem layout (bytes):
//   [0, 91520)        whg_s float4[88*65] (per-pass tile)
//                     / xpart float[4][128*18] (36864B) after phase 2
//   [91520, 100224)   emb_i float4[32*17]  (idx = d4*17 + slot(b))
//                     / x_s float[16*128] after phase 3
//   [100224, 111488)  a_t float[176*16]
//   [111488, 111552)  wacc float[16]
//   [111552, 111556)  flag
// ------------------------------------------------------------------
#define OFF_EMB  91520
#define OFF_AT   100224
#define OFF_WACC 111488
#define OFF_FLAG 111552
#define XPART_IQ 2304      // floats per i-quarter slice: 128*18
#define SMEM_BYTES 111616

__global__ void __launch_bounds__(THREADS, 2) main_kernel(
    const int*   __restrict__ input_ids,
    const int*   __restrict__ target_ids,
    const int*   __restrict__ neg_ids,
    const float* __restrict__ W_in,
    const float* __restrict__ W_out,
    const float* __restrict__ logit_scale,
    float*       __restrict__ out)
{
    extern __shared__ __align__(16) char smem[];
    float4* whg_s = (float4*)smem;
    float*  xpart = (float*)smem;                    // alias after phase 2
    float4* emb_i = (float4*)(smem + OFF_EMB);
    float*  x_s   = (float*)(smem + OFF_EMB);        // alias after phase 3
    float*  a_t   = (float*)(smem + OFF_AT);
    float*  wacc  = (float*)(smem + OFF_WACC);
    int*    sflag = (int*)(smem + OFF_FLAG);

    const int tid  = threadIdx.x;
    const int lane = tid & 31;
    const int warp = tid >> 5;                       // 0..15
    const int b0   = blockIdx.x * BT_;

    // ---- Phase 1: gather + l2-normalize 16 embeddings (1 per warp) ----
    {
        int row = input_ids[b0 + warp];
        float4 v = ((const float4*)(W_in + (size_t)row * D_))[lane];
        float ss = v.x * v.x + v.y * v.y + v.z * v.z + v.w * v.w;
        #pragma unroll
        for (int o = 16; o; o >>= 1) ss += __shfl_xor_sync(0xffffffffu, ss, o);
        float inv = rsqrtf(ss);
        int slot = (warp >> 1) + (warp & 1) * 8;     // even b -> 0..7, odd -> 8..15
        emb_i[lane * 17 + slot] =
            make_float4(v.x * inv, v.y * inv, v.z * inv, v.w * inv);
    }

    // ---- Prefetch phase-4 gather lines into L2 ----
    {
        int gb = b0 + warp;
        if (lane < 24) {
            int j = lane >> 2;
            int row = (j == 0) ? target_ids[gb] : neg_ids[gb * NEG_ + j - 1];
            const float* p = W_out + (size_t)row * D_ + (lane & 3) * 32;
            asm volatile("prefetch.global.L2 [%0];" :: "l"(p));
        } else if (lane < 30) {
            int j = lane - 24;
            int row = (j == 0) ? target_ids[gb] : neg_ids[gb * NEG_ + j - 1];
            const float* p = logit_scale + row;
            asm volatile("prefetch.global.L2 [%0];" :: "l"(p));
        }
    }

    // ---- Phase 2: two passes over i (88 rows each, rows >=170 are zero) ----
    #pragma unroll 1
    for (int p = 0; p < 2; p++) {
        const float4* src = g_WhgP + p * 88 * 65;
        #pragma unroll 1
        for (int f = tid; f < 88 * 65; f += THREADS)
            whg_s[f] = src[f];
        __syncthreads();

        if (tid < 352) {                 // 44 i-pairs x 8 b-pair groups
            int bg = tid & 7;            // b's: 2bg (even), 2bg+1 (odd)
            int lp = tid >> 3;           // local i-pair 0..43
            const ulonglong2* w0 = (const ulonglong2*)&whg_s[(2 * lp) * 65];
            const ulonglong2* w1 = (const ulonglong2*)&whg_s[(2 * lp + 1) * 65];
            const ulonglong2* eb = (const ulonglong2*)emb_i;
            u64 h0e = 0, h0o = 0, h1e = 0, h1o = 0;
            u64 g0e = 0, g0o = 0, g1e = 0, g1o = 0;
            #pragma unroll 4
            for (int d4 = 0; d4 < 32; d4++) {
                ulonglong2 wh0 = w0[d4 * 2];
                ulonglong2 wg0 = w0[d4 * 2 + 1];
                ulonglong2 wh1 = w1[d4 * 2];
                ulonglong2 wg1 = w1[d4 * 2 + 1];
                ulonglong2 e0 = eb[d4 * 17 + bg];        // b even
                ulonglong2 e1 = eb[d4 * 17 + 8 + bg];    // b odd
                h0e = fma2(e0.x, wh0.x, h0e); h0e = fma2(e0.y, wh0.y, h0e);
                h0o = fma2(e1.x, wh0.x, h0o); h0o = fma2(e1.y, wh0.y, h0o);
                h1e = fma2(e0.x, wh1.x, h1e); h1e = fma2(e0.y, wh1.y, h1e);
                h1o = fma2(e1.x, wh1.x, h1o); h1o = fma2(e1.y, wh1.y, h1o);
                g0e = fma2(e0.x, wg0.x, g0e); g0e = fma2(e0.y, wg0.y, g0e);
                g0o = fma2(e1.x, wg0.x, g0o); g0o = fma2(e1.y, wg0.y, g0o);
                g1e = fma2(e0.x, wg1.x, g1e); g1e = fma2(e0.y, wg1.y, g1e);
                g1o = fma2(e1.x, wg1.x, g1o); g1o = fma2(e1.y, wg1.y, g1o);
            }
            int gi = p * 88 + 2 * lp;
            a_t[gi * 16 + 2 * bg]           = silu_mul(h0e, g0e);
            a_t[gi * 16 + 2 * bg + 1]       = silu_mul(h0o, g0o);
            a_t[(gi + 1) * 16 + 2 * bg]     = silu_mul(h1e, g1e);
            a_t[(gi + 1) * 16 + 2 * bg + 1] = silu_mul(h1o, g1o);
        }
        __syncthreads();
    }

    // ---- Phase 3: thread = (d, i-quarter of 44); W from gmem (coalesced, L2) ----
    {
        int d  = tid & 127;
        int iq = tid >> 7;               // 0..3
        const float* wbase = g_WffT + (iq * 44) * D_ + d;
        const ulonglong2* ap = (const ulonglong2*)(a_t + (iq * 44) * 16);
        u64 acc[8] = {0,0,0,0,0,0,0,0};
        #pragma unroll 4
        for (int it = 0; it < 44; it++) {
            float w = __ldg(wbase + it * D_);       // 1 line per warp per it
            u64 ww = pk2(w, w);
            ulonglong2 a0 = ap[it * 4 + 0];         // broadcast LDS.128 (16 b)
            ulonglong2 a1 = ap[it * 4 + 1];
            ulonglong2 a2 = ap[it * 4 + 2];
            ulonglong2 a3 = ap[it * 4 + 3];
            acc[0] = fma2(a0.x, ww, acc[0]);
            acc[1] = fma2(a0.y, ww, acc[1]);
            acc[2] = fma2(a1.x, ww, acc[2]);
            acc[3] = fma2(a1.y, ww, acc[3]);
            acc[4] = fma2(a2.x, ww, acc[4]);
            acc[5] = fma2(a2.y, ww, acc[5]);
            acc[6] = fma2(a3.x, ww, acc[6]);
            acc[7] = fma2(a3.y, ww, acc[7]);
        }
        float* xp = xpart + iq * XPART_IQ + d * 18;
        #pragma unroll
        for (int k = 0; k < 8; k++)
            *(u64*)(xp + 2 * k) = acc[k];
    }

    // ---- Phase-4 gathers (x-independent; hide under reduce) ----
    float4 wv[6];
    float  lsc[6];
    {
        int gb = b0 + warp;
        int rows4[6];
        #pragma unroll
        for (int j = 0; j < 6; j++)
            rows4[j] = (j == 0) ? target_ids[gb] : neg_ids[gb * NEG_ + (j - 1)];
        #pragma unroll
        for (int j = 0; j < 6; j++)
            wv[j] = ((const float4*)(W_out + (size_t)rows4[j] * D_))[lane];
        #pragma unroll
        for (int j = 0; j < 6; j++) lsc[j] = logit_scale[rows4[j]];
    }
    __syncthreads();

    // ---- Reduce i-quarters: x_s[b*128+d] = sum_iq xpart[iq][d*18+b] ----
    #pragma unroll
    for (int r = 0; r < 4; r++) {
        int idx = tid + r * THREADS;     // 2048 outputs
        int b = idx >> 7, d = idx & 127;
        const float* p = xpart + d * 18 + b;
        x_s[b * 128 + d] = p[0] + p[XPART_IQ] + p[2 * XPART_IQ] + p[3 * XPART_IQ];
    }
    __syncthreads();

    // ---- Phase 4: 6 logits per row; warp = 1 batch row ----
    float local = 0.f;
    {
        float4 x4 = ((const float4*)(x_s + warp * 128))[lane];
        #pragma unroll
        for (int j = 0; j < 6; j++) {
            float dot = wv[j].x * x4.x + wv[j].y * x4.y + wv[j].z * x4.z + wv[j].w * x4.w;
            float ss  = wv[j].x * wv[j].x + wv[j].y * wv[j].y + wv[j].z * wv[j].z + wv[j].w * wv[j].w;
            #pragma unroll
            for (int o = 16; o; o >>= 1) {
                dot += __shfl_xor_sync(0xffffffffu, dot, o);
                ss  += __shfl_xor_sync(0xffffffffu, ss, o);
            }
            if (lane == 0) {
                float logit = dot * rsqrtf(ss) * lsc[j] * SQRTD;
                float z = (j == 0) ? logit : -logit;
                float ls = fminf(z, 0.f) - log1pf(__expf(-fabsf(z)));
                local += ls * ((j == 0) ? (1.f / B_) : (1.f / (B_ * NEG_)));
            }
        }
    }
    if (lane == 0) wacc[warp] = local;
    __syncthreads();

    // ---- block partial + fused deterministic final reduction ----
    if (tid == 0) {
        float s = 0.f;
        #pragma unroll
        for (int w = 0; w < 16; w++) s += wacc[w];
        g_partial[blockIdx.x] = s;
        __threadfence();
        unsigned int t = atomicAdd(&g_ticket, 1u);
        sflag[0] = (t == NBLK - 1) ? 1 : 0;
    }
    __syncthreads();
    if (sflag[0]) {
        __threadfence();
        float* red = a_t;                // 256 floats fit
        if (tid < NBLK) red[tid] = g_partial[tid];
        __syncthreads();
        #pragma unroll
        for (int o = NBLK / 2; o; o >>= 1) {
            if (tid < o) red[tid] += red[tid + o];
            __syncthreads();
        }
        if (tid == 0) {
            out[0] = -red[0];
            g_ticket = 0;                // reset for next graph replay
        }
    }
}

extern "C" void kernel_launch(void* const* d_in, const int* in_sizes, int n_in,
                              void* d_out, int out_size)
{
    const int*   input_ids   = (const int*)  d_in[0];
    const int*   target_ids  = (const int*)  d_in[1];
    const int*   neg_ids     = (const int*)  d_in[2];
    const float* W_in        = (const float*)d_in[3];
    const float* W_out       = (const float*)d_in[4];
    const float* W_hidden    = (const float*)d_in[5];
    const float* W_gate      = (const float*)d_in[6];
    const float* W_ff_out    = (const float*)d_in[7];
    const float* hidden_sc   = (const float*)d_in[8];
    const float* gate_sc     = (const float*)d_in[9];
    const float* logit_scale = (const float*)d_in[10];
    float* out = (float*)d_out;

    cudaFuncSetAttribute(main_kernel, cudaFuncAttributeMaxDynamicSharedMemorySize, SMEM_BYTES);

    prep_kernel<<<DIP_, 96>>>(W_hidden, W_gate, W_ff_out, hidden_sc, gate_sc);
    main_kernel<<<NBLK, THREADS, SMEM_BYTES>>>(input_ids, target_ids, neg_ids,
                                               W_in, W_out, logit_scale, out);
}

// round 13
// speedup vs baseline: 1.1319x; 1.1319x over previous
#include <cuda_runtime.h>
#include <math.h>

#define V_   100000
#define D_   128
#define B_   4096
#define NEG_ 5
#define DI_  170
#define DIP_ 176
#define BT_  32
#define NBLK (B_ / BT_)      // 128
#define THREADS 1024
#define SQRTD 11.3137084989847604f

typedef unsigned long long u64;

__device__ __forceinline__ u64 fma2(u64 a, u64 b, u64 c) {
    u64 d;
    asm("fma.rn.f32x2 %0, %1, %2, %3;" : "=l"(d) : "l"(a), "l"(b), "l"(c));
    return d;
}
__device__ __forceinline__ u64 pk2(float lo, float hi) {
    u64 r;
    asm("mov.b64 %0, {%1, %2};" : "=l"(r) : "f"(lo), "f"(hi));
    return r;
}
__device__ __forceinline__ float2 unpk(u64 v) {
    float2 r;
    asm("mov.b64 {%0, %1}, %2;" : "=f"(r.x), "=f"(r.y) : "l"(v));
    return r;
}

// ---- device scratch (prep-written, main-exact layouts) ----
__device__ __align__(16) float4 g_WhgP[DI_ * 65];    // interleaved normalized Wh/Wg
__device__ __align__(16) float  g_WffT[DIP_ * D_];   // transposed inv-prescaled Wff (rows >=170 zero)
__device__ float g_partial[NBLK];
__device__ unsigned int g_ticket;

// ------------------------------------------------------------------
// Prep: 176 blocks x 96 threads (warp0 Wh row, warp1 Wg row, warp2 WffT row).
// ------------------------------------------------------------------
__global__ __launch_bounds__(96) void prep_kernel(
    const float* __restrict__ Wh, const float* __restrict__ Wg,
    const float* __restrict__ Wff,
    const float* __restrict__ hs, const float* __restrict__ gs)
{
    int r    = blockIdx.x;               // 0..175
    int mat  = threadIdx.x >> 5;
    int lane = threadIdx.x & 31;

    if (mat < 2) {
        if (r < DI_) {
            const float4* W = (const float4*)(mat ? Wg : Wh);
            float4 v = W[r * 32 + lane];
            float ss = v.x * v.x + v.y * v.y + v.z * v.z + v.w * v.w;
            #pragma unroll
            for (int o = 16; o; o >>= 1) ss += __shfl_xor_sync(0xffffffffu, ss, o);
            float sc = rsqrtf(ss) * (mat ? gs[r] * SQRTD : hs[r]);
            g_WhgP[r * 65 + lane * 2 + mat] =
                make_float4(v.x * sc, v.y * sc, v.z * sc, v.w * sc);
        }
    } else {
        if (r < DI_) {
            float v[4]; float ss = 0.f;
            #pragma unroll
            for (int k = 0; k < 4; k++) {
                v[k] = Wff[(lane + 32 * k) * DI_ + r];
                ss += v[k] * v[k];
            }
            #pragma unroll
            for (int o = 16; o; o >>= 1) ss += __shfl_xor_sync(0xffffffffu, ss, o);
            float inv = rsqrtf(ss);
            #pragma unroll
            for (int k = 0; k < 4; k++)
                g_WffT[r * D_ + lane + 32 * k] = v[k] * inv;
        } else {
            #pragma unroll
            for (int k = 0; k < 4; k++)
                g_WffT[r * D_ + lane + 32 * k] = 0.f;
        }
    }
}

// ------------------------------------------------------------------
// Main: 128 blocks x 1024 threads, 32 batch rows/block (R11 structure).
//
// smem layout (bytes):
//   [0, 176800)       whg_s float4[170*65]
//     after phase 2, aliased as xpart float[4][128*34] (69632B)
//   [176800, 193184)  emb_i float4[1024]  / x_s[32][128] after phase 3
//   [193184, 215712)  a_t float[176*32]   (rows 170-175 zeroed)
//   [216416, 216544)  wacc float[32]
//   [216544, 216548)  flag
// ------------------------------------------------------------------
#define XPART_IQ   4352
#define SMEM_BYTES 216576

__global__ void __launch_bounds__(THREADS) main_kernel(
    const int*   __restrict__ input_ids,
    const int*   __restrict__ target_ids,
    const int*   __restrict__ neg_ids,
    const float* __restrict__ W_in,
    const float* __restrict__ W_out,
    const float* __restrict__ logit_scale,
    float*       __restrict__ out)
{
    extern __shared__ __align__(16) char smem[];
    float4* whg_s = (float4*)smem;
    float*  xpart = (float*)smem;                    // alias after phase 2
    float4* emb_i = (float4*)(smem + 176800);
    float*  x_s   = (float*)(smem + 176800);         // alias after phase 3
    float*  a_t   = (float*)(smem + 193184);
    float*  wacc  = (float*)(smem + 216416);
    int*    sflag = (int*)(smem + 216544);

    const int tid  = threadIdx.x;
    const int lane = tid & 31;
    const int warp = tid >> 5;
    const int b0   = blockIdx.x * BT_;

    // ---- Async bulk copy whg (LDGSTS, fire-and-forget; wait before ph2) ----
    {
        unsigned int sbase = (unsigned int)__cvta_generic_to_shared(whg_s);
        #pragma unroll 1
        for (int f = tid; f < DI_ * 65; f += THREADS) {
            asm volatile("cp.async.cg.shared.global [%0], [%1], 16;"
                         :: "r"(sbase + f * 16), "l"(g_WhgP + f));
        }
        asm volatile("cp.async.commit_group;");
    }

    // ---- Phase 1: gather + l2-normalize 32 input embeddings (1 per warp) ----
    {
        int row = input_ids[b0 + warp];
        float4 v = ((const float4*)(W_in + (size_t)row * D_))[lane];
        float ss = v.x * v.x + v.y * v.y + v.z * v.z + v.w * v.w;
        #pragma unroll
        for (int o = 16; o; o >>= 1) ss += __shfl_xor_sync(0xffffffffu, ss, o);
        float inv = rsqrtf(ss);
        emb_i[lane * 32 + (warp & 3) * 8 + (warp >> 2)] =
            make_float4(v.x * inv, v.y * inv, v.z * inv, v.w * inv);
    }

    // ---- Prefetch phase-4 gather lines into L2 ----
    {
        int gb = b0 + warp;
        if (lane < 24) {
            int j = lane >> 2;
            int row = (j == 0) ? target_ids[gb] : neg_ids[gb * NEG_ + j - 1];
            const float* p = W_out + (size_t)row * D_ + (lane & 3) * 32;
            asm volatile("prefetch.global.L2 [%0];" :: "l"(p));
        } else if (lane < 30) {
            int j = lane - 24;
            int row = (j == 0) ? target_ids[gb] : neg_ids[gb * NEG_ + j - 1];
            const float* p = logit_scale + row;
            asm volatile("prefetch.global.L2 [%0];" :: "l"(p));
        }
    }
    asm volatile("cp.async.wait_group 0;");
    __syncthreads();

    // ---- Phase 2: a[b][i]=silu(g)*h; thread = (i-pair, 4-b group) ----
    if (tid < 85 * 8) {
        int bg = tid & 7;
        int pp = tid >> 3;              // 0..84 -> rows i0 = 2pp, 2pp+1
        const ulonglong2* w0 = (const ulonglong2*)&whg_s[(2 * pp) * 65];
        const ulonglong2* w1 = (const ulonglong2*)&whg_s[(2 * pp + 1) * 65];
        const ulonglong2* eb = (const ulonglong2*)emb_i;
        u64 h0[4] = {0,0,0,0}, g0[4] = {0,0,0,0};
        u64 h1[4] = {0,0,0,0}, g1[4] = {0,0,0,0};
        #pragma unroll 2
        for (int d4 = 0; d4 < 32; d4++) {
            ulonglong2 wh0 = w0[d4 * 2];
            ulonglong2 wg0 = w0[d4 * 2 + 1];
            ulonglong2 wh1 = w1[d4 * 2];
            ulonglong2 wg1 = w1[d4 * 2 + 1];
            #pragma unroll
            for (int k = 0; k < 4; k++) {
                ulonglong2 ev = eb[d4 * 32 + k * 8 + bg];
                h0[k] = fma2(ev.x, wh0.x, h0[k]);
                h0[k] = fma2(ev.y, wh0.y, h0[k]);
                g0[k] = fma2(ev.x, wg0.x, g0[k]);
                g0[k] = fma2(ev.y, wg0.y, g0[k]);
                h1[k] = fma2(ev.x, wh1.x, h1[k]);
                h1[k] = fma2(ev.y, wh1.y, h1[k]);
                g1[k] = fma2(ev.x, wg1.x, g1[k]);
                g1[k] = fma2(ev.y, wg1.y, g1[k]);
            }
        }
        #pragma unroll
        for (int k = 0; k < 4; k++) {
            float2 hp = unpk(h0[k]); float2 gp = unpk(g0[k]);
            float h = hp.x + hp.y, g = gp.x + gp.y;
            a_t[(2 * pp) * 32 + 4 * bg + k] = h * (g / (1.f + __expf(-g)));
            hp = unpk(h1[k]); gp = unpk(g1[k]);
            h = hp.x + hp.y; g = gp.x + gp.y;
            a_t[(2 * pp + 1) * 32 + 4 * bg + k] = h * (g / (1.f + __expf(-g)));
        }
    } else if (tid >= 832) {                 // zero a_t pad rows (192 floats)
        a_t[DI_ * 32 + (tid - 832)] = 0.f;
    }
    __syncthreads();

    // ---- Phase 3: thread = (d, 16-b half, i-quarter of 44); W direct from gmem ----
    {
        int d   = tid & 127;
        int grp = tid >> 7;            // 0..7
        int bg  = grp & 1;             // b half: b0 = bg*16
        int iq  = grp >> 1;            // i quarter (44 each; rows >=170 zero)
        int i0  = iq * 44;
        u64 acc[8] = {0,0,0,0,0,0,0,0};
        const float* wbase = g_WffT + i0 * D_ + d;      // coalesced per warp
        const ulonglong2* ap = (const ulonglong2*)(a_t + i0 * 32 + bg * 16);
        #pragma unroll 4
        for (int it = 0; it < 44; it++) {
            float w = __ldg(wbase + it * D_);
            u64 ww = pk2(w, w);
            ulonglong2 a0 = ap[it * 8 + 0];             // broadcast LDS.128
            ulonglong2 a1 = ap[it * 8 + 1];
            ulonglong2 a2 = ap[it * 8 + 2];
            ulonglong2 a3 = ap[it * 8 + 3];
            acc[0] = fma2(a0.x, ww, acc[0]);
            acc[1] = fma2(a0.y, ww, acc[1]);
            acc[2] = fma2(a1.x, ww, acc[2]);
            acc[3] = fma2(a1.y, ww, acc[3]);
            acc[4] = fma2(a2.x, ww, acc[4]);
            acc[5] = fma2(a2.y, ww, acc[5]);
            acc[6] = fma2(a3.x, ww, acc[6]);
            acc[7] = fma2(a3.y, ww, acc[7]);
        }
        float* xp = xpart + iq * XPART_IQ + d * 34 + bg * 16;
        #pragma unroll
        for (int k = 0; k < 8; k++)
            *(u64*)(xp + 2 * k) = acc[k];
    }

    // ---- Phase-4 gathers (x-independent; hide under reduce) ----
    float4 wv[6];
    float  lsc[6];
    {
        int gb = b0 + warp;
        int rows4[6];
        #pragma unroll
        for (int j = 0; j < 6; j++)
            rows4[j] = (j == 0) ? target_ids[gb] : neg_ids[gb * NEG_ + (j - 1)];
        #pragma unroll
        for (int j = 0; j < 6; j++)
            wv[j] = ((const float4*)(W_out + (size_t)rows4[j] * D_))[lane];
        #pragma unroll
        for (int j = 0; j < 6; j++) lsc[j] = logit_scale[rows4[j]];
    }
    __syncthreads();

    // ---- Reduce i-quarters: x_s[b*128+d] = sum_iq xpart[iq][d*34+b] ----
    #pragma unroll
    for (int r = 0; r < 4; r++) {
        int idx = tid + r * THREADS;       // 4096 outputs
        int b = idx >> 7, d = idx & 127;
        const float* p = xpart + d * 34 + b;
        float s = p[0] + p[XPART_IQ] + p[2 * XPART_IQ] + p[3 * XPART_IQ];
        x_s[b * 128 + d] = s;
    }
    __syncthreads();

    // ---- Phase 4: 6 logits per row; warp = 1 batch row ----
    float local = 0.f;
    {
        float4 x4 = ((const float4*)(x_s + warp * 128))[lane];
        #pragma unroll
        for (int j = 0; j < 6; j++) {
            float dot = wv[j].x * x4.x + wv[j].y * x4.y + wv[j].z * x4.z + wv[j].w * x4.w;
            float ss  = wv[j].x * wv[j].x + wv[j].y * wv[j].y + wv[j].z * wv[j].z + wv[j].w * wv[j].w;
            #pragma unroll
            for (int o = 16; o; o >>= 1) {
                dot += __shfl_xor_sync(0xffffffffu, dot, o);
                ss  += __shfl_xor_sync(0xffffffffu, ss, o);
            }
            if (lane == 0) {
                float logit = dot * rsqrtf(ss) * lsc[j] * SQRTD;
                float z = (j == 0) ? logit : -logit;
                float ls = fminf(z, 0.f) - log1pf(__expf(-fabsf(z)));
                local += ls * ((j == 0) ? (1.f / B_) : (1.f / (B_ * NEG_)));
            }
        }
    }
    if (lane == 0) wacc[warp] = local;
    __syncthreads();

    // ---- block partial + fused deterministic final reduction ----
    if (tid == 0) {
        float s = 0.f;
        #pragma unroll
        for (int w = 0; w < 32; w++) s += wacc[w];
        g_partial[blockIdx.x] = s;
        __threadfence();
        unsigned int t = atomicAdd(&g_ticket, 1u);
        sflag[0] = (t == NBLK - 1) ? 1 : 0;
    }
    __syncthreads();
    if (sflag[0]) {
        __threadfence();
        float* red = a_t;  // reuse smem
        if (tid < NBLK) red[tid] = g_partial[tid];
        __syncthreads();
        #pragma unroll
        for (int o = NBLK / 2; o; o >>= 1) {
            if (tid < o) red[tid] += red[tid + o];
            __syncthreads();
        }
        if (tid == 0) {
            out[0] = -red[0];
            g_ticket = 0;   // reset for next graph replay
        }
    }
}

extern "C" void kernel_launch(void* const* d_in, const int* in_sizes, int n_in,
                              void* d_out, int out_size)
{
    const int*   input_ids   = (const int*)  d_in[0];
    const int*   target_ids  = (const int*)  d_in[1];
    const int*   neg_ids     = (const int*)  d_in[2];
    const float* W_in        = (const float*)d_in[3];
    const float* W_out       = (const float*)d_in[4];
    const float* W_hidden    = (const float*)d_in[5];
    const float* W_gate      = (const float*)d_in[6];
    const float* W_ff_out    = (const float*)d_in[7];
    const float* hidden_sc   = (const float*)d_in[8];
    const float* gate_sc     = (const float*)d_in[9];
    const float* logit_scale = (const float*)d_in[10];
    float* out = (float*)d_out;

    cudaFuncSetAttribute(main_kernel, cudaFuncAttributeMaxDynamicSharedMemorySize, SMEM_BYTES);

    prep_kernel<<<DIP_, 96>>>(W_hidden, W_gate, W_ff_out, hidden_sc, gate_sc);
    main_kernel<<<NBLK, THREADS, SMEM_BYTES>>>(input_ids, target_ids, neg_ids,
                                               W_in, W_out, logit_scale, out);
}

// round 14
// speedup vs baseline: 1.7927x; 1.5838x over previous
#include <cuda_runtime.h>
#include <math.h>

#define V_   100000
#define D_   128
#define B_   4096
#define NEG_ 5
#define DI_  170
#define DIP_ 176
#define BT_  32
#define NBLK (B_ / BT_)      // 128
#define THREADS 1024
#define SQRTD 11.3137084989847604f

#define NW   344             // whgT row stride / padded N (n = 2i+mat)
#define ATS  40              // a_t row stride (rows = i, cols = b)
#define XSS  136             // x_s row stride
#define WFS  136             // wff_s row stride

typedef unsigned long long u64;

__device__ __forceinline__ unsigned f2tf32(float f) {
    unsigned u;
    asm("cvt.rna.tf32.f32 %0, %1;" : "=r"(u) : "f"(f));
    return u;
}
__device__ __forceinline__ void mma_tf32(float c[4],
    unsigned a0, unsigned a1, unsigned a2, unsigned a3,
    unsigned b0, unsigned b1)
{
    asm volatile(
        "mma.sync.aligned.m16n8k8.row.col.f32.tf32.tf32.f32 "
        "{%0,%1,%2,%3}, {%4,%5,%6,%7}, {%8,%9}, {%0,%1,%2,%3};"
        : "+f"(c[0]), "+f"(c[1]), "+f"(c[2]), "+f"(c[3])
        : "r"(a0), "r"(a1), "r"(a2), "r"(a3), "r"(b0), "r"(b1));
}

// ---- device scratch (prep-written, tf32-rounded, main-exact layouts) ----
__device__ __align__(16) float g_WhgT[D_ * NW];      // [d][n], n=2i+mat, cols>=340 zero
__device__ __align__(16) float g_WffT[DIP_ * D_];    // [i][d], inv-prescaled, rows>=170 zero
__device__ float g_partial[NBLK];
__device__ unsigned int g_ticket;

// ------------------------------------------------------------------
// Prep: 176 blocks x 96 threads.
//  warp0/1: Wh/Wg row r -> normalized, scaled, tf32 -> whgT column 2r+mat
//  warp2:   Wff column r -> normalized (over d), tf32 -> WffT row r
// ------------------------------------------------------------------
__global__ __launch_bounds__(96) void prep_kernel(
    const float* __restrict__ Wh, const float* __restrict__ Wg,
    const float* __restrict__ Wff,
    const float* __restrict__ hs, const float* __restrict__ gs)
{
    int r    = blockIdx.x;               // 0..175
    int mat  = threadIdx.x >> 5;
    int lane = threadIdx.x & 31;

    if (mat < 2) {
        if (r < DI_) {
            const float4* W = (const float4*)(mat ? Wg : Wh);
            float4 v = W[r * 32 + lane];
            float ss = v.x * v.x + v.y * v.y + v.z * v.z + v.w * v.w;
            #pragma unroll
            for (int o = 16; o; o >>= 1) ss += __shfl_xor_sync(0xffffffffu, ss, o);
            float sc = rsqrtf(ss) * (mat ? gs[r] * SQRTD : hs[r]);
            float vv[4] = {v.x * sc, v.y * sc, v.z * sc, v.w * sc};
            #pragma unroll
            for (int k = 0; k < 4; k++)
                g_WhgT[(lane * 4 + k) * NW + 2 * r + mat] =
                    __uint_as_float(f2tf32(vv[k]));
        } else if (r < DI_ + 2) {        // zero pad cols 340..343
            #pragma unroll
            for (int k = 0; k < 4; k++)
                g_WhgT[(lane * 4 + k) * NW + 2 * r + mat] = 0.f;
        }
    } else {
        if (r < DI_) {
            float v[4]; float ss = 0.f;
            #pragma unroll
            for (int k = 0; k < 4; k++) {
                v[k] = Wff[(lane + 32 * k) * DI_ + r];
                ss += v[k] * v[k];
            }
            #pragma unroll
            for (int o = 16; o; o >>= 1) ss += __shfl_xor_sync(0xffffffffu, ss, o);
            float inv = rsqrtf(ss);
            #pragma unroll
            for (int k = 0; k < 4; k++)
                g_WffT[r * D_ + lane + 32 * k] =
                    __uint_as_float(f2tf32(v[k] * inv));
        } else {
            #pragma unroll
            for (int k = 0; k < 4; k++)
                g_WffT[r * D_ + lane + 32 * k] = 0.f;
        }
    }
}

// ------------------------------------------------------------------
// Main: 128 blocks x 1024 threads, 32 batch rows/block.
// Phases 2+3 on tensor cores (mma.sync m16n8k8 tf32).
//
// smem layout (bytes):
//   [0, 176128)       whgT float[128][344]
//                     / wff_s float[176][136] (95744B) after phase 2
//   [176128, 193536)  emb_s float[32][132] / x_s float[32][136] after ph2
//   [193536, 221696)  a_t float[176][40]  (i-major, tf32 values)
//   [221696, 221824)  wacc float[32]
//   [221824, 221828)  flag
// ------------------------------------------------------------------
#define OFF_EMB  176128
#define OFF_AT   193536
#define OFF_WACC 221696
#define OFF_FLAG 221824
#define SMEM_BYTES 221952

__global__ void __launch_bounds__(THREADS) main_kernel(
    const int*   __restrict__ input_ids,
    const int*   __restrict__ target_ids,
    const int*   __restrict__ neg_ids,
    const float* __restrict__ W_in,
    const float* __restrict__ W_out,
    const float* __restrict__ logit_scale,
    float*       __restrict__ out)
{
    extern __shared__ __align__(16) char smem[];
    float* whgT  = (float*)smem;
    float* wff_s = (float*)smem;                     // alias after phase 2
    float* emb_s = (float*)(smem + OFF_EMB);
    float* x_s   = (float*)(smem + OFF_EMB);         // alias after phase 2
    float* a_t   = (float*)(smem + OFF_AT);
    float* wacc  = (float*)(smem + OFF_WACC);
    int*   sflag = (int*)(smem + OFF_FLAG);

    const int tid  = threadIdx.x;
    const int lane = tid & 31;
    const int warp = tid >> 5;
    const int b0   = blockIdx.x * BT_;

    // ---- Async bulk copy whgT (LDGSTS; wait before phase 2) ----
    {
        unsigned int sbase = (unsigned int)__cvta_generic_to_shared(whgT);
        const float4* src = (const float4*)g_WhgT;
        #pragma unroll 1
        for (int f = tid; f < (D_ * NW) / 4; f += THREADS) {
            asm volatile("cp.async.cg.shared.global [%0], [%1], 16;"
                         :: "r"(sbase + f * 16), "l"(src + f));
        }
        asm volatile("cp.async.commit_group;");
    }

    // ---- Phase 1: gather + l2-normalize + tf32-convert 32 embeddings ----
    {
        int row = input_ids[b0 + warp];
        float4 v = ((const float4*)(W_in + (size_t)row * D_))[lane];
        float ss = v.x * v.x + v.y * v.y + v.z * v.z + v.w * v.w;
        #pragma unroll
        for (int o = 16; o; o >>= 1) ss += __shfl_xor_sync(0xffffffffu, ss, o);
        float inv = rsqrtf(ss);
        float4 o4;
        o4.x = __uint_as_float(f2tf32(v.x * inv));
        o4.y = __uint_as_float(f2tf32(v.y * inv));
        o4.z = __uint_as_float(f2tf32(v.z * inv));
        o4.w = __uint_as_float(f2tf32(v.w * inv));
        ((float4*)emb_s)[warp * 33 + lane] = o4;     // stride 132 floats
    }

    // ---- Prefetch phase-4 gather lines into L2 ----
    {
        int gb = b0 + warp;
        if (lane < 24) {
            int j = lane >> 2;
            int row = (j == 0) ? target_ids[gb] : neg_ids[gb * NEG_ + j - 1];
            const float* p = W_out + (size_t)row * D_ + (lane & 3) * 32;
            asm volatile("prefetch.global.L2 [%0];" :: "l"(p));
        } else if (lane < 30) {
            int j = lane - 24;
            int row = (j == 0) ? target_ids[gb] : neg_ids[gb * NEG_ + j - 1];
            const float* p = logit_scale + row;
            asm volatile("prefetch.global.L2 [%0];" :: "l"(p));
        }
    }
    asm volatile("cp.async.wait_group 0;");
    __syncthreads();

    // ================= Phase 2: [32x344] = emb @ whgT via mma =================
    // warp = (m = warp&1, ns = warp>>1); tiles nt = ns, ns+16 (+ns+32 if ns<11)
    {
        int m  = warp & 1;
        int ns = warp >> 1;
        int g  = lane >> 2, t = lane & 3;
        float c0[4] = {0.f,0.f,0.f,0.f};
        float c1[4] = {0.f,0.f,0.f,0.f};
        float c2[4] = {0.f,0.f,0.f,0.f};
        const bool has3 = (ns < 11);
        const float* As = emb_s + (m * 16 + g) * 132 + t;
        const float* Bs = whgT + t * NW + ns * 8 + g;
        #pragma unroll 4
        for (int k = 0; k < 16; k++) {
            unsigned a0 = __float_as_uint(As[k * 8]);
            unsigned a1 = __float_as_uint(As[k * 8 + 8 * 132]);
            unsigned a2 = __float_as_uint(As[k * 8 + 4]);
            unsigned a3 = __float_as_uint(As[k * 8 + 8 * 132 + 4]);
            const float* Bk = Bs + k * 8 * NW;
            unsigned b0 = __float_as_uint(Bk[0]);
            unsigned b1 = __float_as_uint(Bk[4 * NW]);
            mma_tf32(c0, a0, a1, a2, a3, b0, b1);
            b0 = __float_as_uint(Bk[128]);
            b1 = __float_as_uint(Bk[4 * NW + 128]);
            mma_tf32(c1, a0, a1, a2, a3, b0, b1);
            if (has3) {
                b0 = __float_as_uint(Bk[256]);
                b1 = __float_as_uint(Bk[4 * NW + 256]);
                mma_tf32(c2, a0, a1, a2, a3, b0, b1);
            }
        }
        // epilogue: c = [h(i), g(i)] pairs; a = h*silu(g), tf32-round, store a_t[i][b]
        int bb = m * 16 + g;
        {
            int i = ns * 4 + t;
            float v0 = c0[0] * (c0[1] / (1.f + __expf(-c0[1])));
            float v1 = c0[2] * (c0[3] / (1.f + __expf(-c0[3])));
            a_t[i * ATS + bb]     = __uint_as_float(f2tf32(v0));
            a_t[i * ATS + bb + 8] = __uint_as_float(f2tf32(v1));
        }
        {
            int i = (ns + 16) * 4 + t;
            float v0 = c1[0] * (c1[1] / (1.f + __expf(-c1[1])));
            float v1 = c1[2] * (c1[3] / (1.f + __expf(-c1[3])));
            a_t[i * ATS + bb]     = __uint_as_float(f2tf32(v0));
            a_t[i * ATS + bb + 8] = __uint_as_float(f2tf32(v1));
        }
        if (has3) {
            int i = (ns + 32) * 4 + t;
            float v0 = c2[0] * (c2[1] / (1.f + __expf(-c2[1])));
            float v1 = c2[2] * (c2[3] / (1.f + __expf(-c2[3])));
            a_t[i * ATS + bb]     = __uint_as_float(f2tf32(v0));
            a_t[i * ATS + bb + 8] = __uint_as_float(f2tf32(v1));
        }
        if (tid < 128)                   // zero a_t rows 172..175
            a_t[(172 + (tid >> 5)) * ATS + (tid & 31)] = 0.f;
    }
    __syncthreads();

    // ---- Stage WffT into smem (stride 136 for conflict-free B-frags) ----
    {
        unsigned int sbase = (unsigned int)__cvta_generic_to_shared(wff_s);
        const float4* src = (const float4*)g_WffT;
        #pragma unroll 1
        for (int f = tid; f < DIP_ * 32; f += THREADS) {
            unsigned int dst = sbase + ((f >> 5) * WFS + (f & 31) * 4) * 4;
            asm volatile("cp.async.cg.shared.global [%0], [%1], 16;"
                         :: "r"(dst), "l"(src + f));
        }
        asm volatile("cp.async.commit_group;");
        asm volatile("cp.async.wait_group 0;");
    }
    __syncthreads();

    // ================= Phase 3: [32x128] = a @ WffT via mma =================
    // warp = (m = warp&1, dt = warp>>1); one 16x8 tile per warp, K=176.
    {
        int m  = warp & 1;
        int dt = warp >> 1;
        int g  = lane >> 2, t = lane & 3;
        float c[4] = {0.f,0.f,0.f,0.f};
        const float* Aa = a_t + t * ATS + m * 16 + g;   // A[b][i] from a_t[i][b]
        const float* Bw = wff_s + t * WFS + dt * 8 + g;
        #pragma unroll 11
        for (int k = 0; k < 22; k++) {
            unsigned a0 = __float_as_uint(Aa[k * 8 * ATS]);
            unsigned a1 = __float_as_uint(Aa[k * 8 * ATS + 8]);
            unsigned a2 = __float_as_uint(Aa[k * 8 * ATS + 4 * ATS]);
            unsigned a3 = __float_as_uint(Aa[k * 8 * ATS + 4 * ATS + 8]);
            unsigned b0 = __float_as_uint(Bw[k * 8 * WFS]);
            unsigned b1 = __float_as_uint(Bw[k * 8 * WFS + 4 * WFS]);
            mma_tf32(c, a0, a1, a2, a3, b0, b1);
        }
        *(float2*)(x_s + (m * 16 + g) * XSS + dt * 8 + 2 * t)     = make_float2(c[0], c[1]);
        *(float2*)(x_s + (m * 16 + g + 8) * XSS + dt * 8 + 2 * t) = make_float2(c[2], c[3]);
    }

    // ---- Phase-4 gathers (x-independent) ----
    float4 wv[6];
    float  lsc[6];
    {
        int gb = b0 + warp;
        int rows4[6];
        #pragma unroll
        for (int j = 0; j < 6; j++)
            rows4[j] = (j == 0) ? target_ids[gb] : neg_ids[gb * NEG_ + (j - 1)];
        #pragma unroll
        for (int j = 0; j < 6; j++)
            wv[j] = ((const float4*)(W_out + (size_t)rows4[j] * D_))[lane];
        #pragma unroll
        for (int j = 0; j < 6; j++) lsc[j] = logit_scale[rows4[j]];
    }
    __syncthreads();

    // ---- Phase 4: 6 logits per row; warp = 1 batch row ----
    float local = 0.f;
    {
        float4 x4 = ((const float4*)(x_s + warp * XSS))[lane];
        #pragma unroll
        for (int j = 0; j < 6; j++) {
            float dot = wv[j].x * x4.x + wv[j].y * x4.y + wv[j].z * x4.z + wv[j].w * x4.w;
            float ss  = wv[j].x * wv[j].x + wv[j].y * wv[j].y + wv[j].z * wv[j].z + wv[j].w * wv[j].w;
            #pragma unroll
            for (int o = 16; o; o >>= 1) {
                dot += __shfl_xor_sync(0xffffffffu, dot, o);
                ss  += __shfl_xor_sync(0xffffffffu, ss, o);
            }
            if (lane == 0) {
                float logit = dot * rsqrtf(ss) * lsc[j] * SQRTD;
                float z = (j == 0) ? logit : -logit;
                float ls = fminf(z, 0.f) - log1pf(__expf(-fabsf(z)));
                local += ls * ((j == 0) ? (1.f / B_) : (1.f / (B_ * NEG_)));
            }
        }
    }
    if (lane == 0) wacc[warp] = local;
    __syncthreads();

    // ---- block partial + fused deterministic final reduction ----
    if (tid == 0) {
        float s = 0.f;
        #pragma unroll
        for (int w = 0; w < 32; w++) s += wacc[w];
        g_partial[blockIdx.x] = s;
        __threadfence();
        unsigned int t = atomicAdd(&g_ticket, 1u);
        sflag[0] = (t == NBLK - 1) ? 1 : 0;
    }
    __syncthreads();
    if (sflag[0]) {
        __threadfence();
        float* red = a_t;  // reuse smem
        if (tid < NBLK) red[tid] = g_partial[tid];
        __syncthreads();
        #pragma unroll
        for (int o = NBLK / 2; o; o >>= 1) {
            if (tid < o) red[tid] += red[tid + o];
            __syncthreads();
        }
        if (tid == 0) {
            out[0] = -red[0];
            g_ticket = 0;   // reset for next graph replay
        }
    }
}

extern "C" void kernel_launch(void* const* d_in, const int* in_sizes, int n_in,
                              void* d_out, int out_size)
{
    const int*   input_ids   = (const int*)  d_in[0];
    const int*   target_ids  = (const int*)  d_in[1];
    const int*   neg_ids     = (const int*)  d_in[2];
    const float* W_in        = (const float*)d_in[3];
    const float* W_out       = (const float*)d_in[4];
    const float* W_hidden    = (const float*)d_in[5];
    const float* W_gate      = (const float*)d_in[6];
    const float* W_ff_out    = (const float*)d_in[7];
    const float* hidden_sc   = (const float*)d_in[8];
    const float* gate_sc     = (const float*)d_in[9];
    const float* logit_scale = (const float*)d_in[10];
    float* out = (float*)d_out;

    cudaFuncSetAttribute(main_kernel, cudaFuncAttributeMaxDynamicSharedMemorySize, SMEM_BYTES);

    prep_kernel<<<DIP_, 96>>>(W_hidden, W_gate, W_ff_out, hidden_sc, gate_sc);
    main_kernel<<<NBLK, THREADS, SMEM_BYTES>>>(input_ids, target_ids, neg_ids,
                                               W_in, W_out, logit_scale, out);
}